// round 5
// baseline (speedup 1.0000x reference)
#include <cuda_runtime.h>
#include <math.h>

// ---------------------------------------------------------------------------
// ViTBlockQuantum, fully fused. Analytic collapse of the 8-qubit VQC:
//   phi_w = in_w + theta_w;  z_k = prod_{w=0..k} cos(phi_w) (k>=1),
//   z_0 = prod_{w=1..7} cos(phi_w)
// One kernel: block = (batch, query-half), 512 threads (128 regs/thread).
//   phase 1: K (thr 0-255), V (thr 256-511); each thread also computes its
//            own query pair's Q in registers (redundant across kh/h).
//   phase 2: attention; thread = (query-pair, head, k-quarter); 2 keys/iter,
//            f32x2-packed, K/V loads amortized over 2 queries.
//   phase 3: per-token tail (consts via __ldg broadcast).
// ---------------------------------------------------------------------------

#define EGS 8
#define SSEQ 256
#define QH 128
// 0.5 (1/sqrt(dk), dk=4) * log2(e): folded into Q so softmax uses ex2 directly
#define QSCALE 0.72134752044448170368f

typedef unsigned long long u64;

__device__ __forceinline__ float ex2f(float x) {
    float y; asm("ex2.approx.ftz.f32 %0, %1;" : "=f"(y) : "f"(x)); return y;
}
__device__ __forceinline__ u64 pk2(float lo, float hi) {
    u64 r; asm("mov.b64 %0, {%1, %2};" : "=l"(r) : "f"(lo), "f"(hi)); return r;
}
__device__ __forceinline__ void upk2(float& lo, float& hi, u64 v) {
    asm("mov.b64 {%0, %1}, %2;" : "=f"(lo), "=f"(hi) : "l"(v));
}
__device__ __forceinline__ u64 mul2(u64 a, u64 b) {
    u64 d; asm("mul.rn.f32x2 %0, %1, %2;" : "=l"(d) : "l"(a), "l"(b)); return d;
}
__device__ __forceinline__ u64 fma2(u64 a, u64 b, u64 c) {
    u64 d; asm("fma.rn.f32x2 %0, %1, %2, %3;" : "=l"(d) : "l"(a), "l"(b), "l"(c)); return d;
}
__device__ __forceinline__ u64 add2(u64 a, u64 b) {
    u64 d; asm("add.rn.f32x2 %0, %1, %2;" : "=l"(d) : "l"(a), "l"(b)); return d;
}

__device__ __forceinline__ void vqc8(const float a[8], float z[8]) {
    float c[8];
#pragma unroll
    for (int w = 0; w < 8; w++) c[w] = __cosf(a[w]);
    float p = c[0];
#pragma unroll
    for (int k = 1; k < 8; k++) { p *= c[k]; z[k] = p; }
    float q = c[1];
#pragma unroll
    for (int w = 2; w < 8; w++) q *= c[w];
    z[0] = q;
}

// paired K/V smem layout: keys 2k,2k+1 interleaved so one ulonglong2 load
// yields two f32x2 operands (d,d+1 for both keys) with zero pack movs
__device__ __forceinline__ int kvidx(int k, int d) {
    return (k >> 1) * 16 + (d >> 2) * 8 + ((d & 2) << 1) + ((d & 1) << 1) + (k & 1);
}

__global__ void __launch_bounds__(512) fused_kernel(
    const float* __restrict__ x,
    const float* __restrict__ Wq, const float* __restrict__ Wk,
    const float* __restrict__ Wv, const float* __restrict__ Wc,
    const float* __restrict__ Wf,
    const float* __restrict__ w1, const float* __restrict__ b1,
    const float* __restrict__ w2, const float* __restrict__ b2,
    const float* __restrict__ g1, const float* __restrict__ be1,
    const float* __restrict__ g2, const float* __restrict__ be2,
    float* __restrict__ out)
{
    __shared__ __align__(16) float Ks[SSEQ * 8];
    __shared__ __align__(16) float Vs[SSEQ * 8];
    __shared__ float Ctx[QH * 8];
    __shared__ float Part[3 * 256 * 5];   // kh=1..3 partials, 256 (q,h) units

    const int b   = blockIdx.x >> 1;
    const int qh  = blockIdx.x & 1;
    const int tid = threadIdx.x;
    const int qp  = tid & 63;          // query pair 0..63
    const int h   = (tid >> 6) & 1;    // head
    const int kh  = tid >> 7;          // k-quarter 0..3

    // prefetch tail x (tid<128) to hide global latency behind phase 2
    float4 px0 = make_float4(0.f, 0.f, 0.f, 0.f), px1 = px0;
    if (tid < QH) {
        const float4* xt = (const float4*)(x + (size_t)(b * SSEQ + qh * QH + tid) * EGS);
        px0 = xt[0]; px1 = xt[1];
    }

    // ---------------- phase 1: K (0-255) / V (256-511) ----------------
    {
        const int t = tid & 255;
        const int isV = tid >> 8;
        const float* W = isV ? Wv : Wk;
        const float4* xt = (const float4*)(x + (size_t)(b * SSEQ + t) * EGS);
        float4 x0 = xt[0], x1 = xt[1];
        float a[8], z[8];
        a[0] = x0.x + __ldg(W + 0); a[1] = x0.y + __ldg(W + 1);
        a[2] = x0.z + __ldg(W + 2); a[3] = x0.w + __ldg(W + 3);
        a[4] = x1.x + __ldg(W + 4); a[5] = x1.y + __ldg(W + 5);
        a[6] = x1.z + __ldg(W + 6); a[7] = x1.w + __ldg(W + 7);
        vqc8(a, z);
        float* dst = isV ? Vs : Ks;
#pragma unroll
        for (int d = 0; d < 8; d++) dst[kvidx(t, d)] = z[d];
    }

    // Q for this thread's two queries, in registers (redundant across kh)
    u64 q0p0, q0p1, q0p2, q0p3, q1p0, q1p1, q1p2, q1p3;
    {
        const size_t tq = (size_t)(b * SSEQ + qh * QH + qp * 2) * EGS;
        const float4* xt = (const float4*)(x + tq);
        float a[8], z[8];
        float4 x0 = xt[0], x1 = xt[1];
        a[0] = x0.x + __ldg(Wq + 0); a[1] = x0.y + __ldg(Wq + 1);
        a[2] = x0.z + __ldg(Wq + 2); a[3] = x0.w + __ldg(Wq + 3);
        a[4] = x1.x + __ldg(Wq + 4); a[5] = x1.y + __ldg(Wq + 5);
        a[6] = x1.z + __ldg(Wq + 6); a[7] = x1.w + __ldg(Wq + 7);
        vqc8(a, z);
        q0p0 = pk2(z[h*4+0]*QSCALE, z[h*4+0]*QSCALE);
        q0p1 = pk2(z[h*4+1]*QSCALE, z[h*4+1]*QSCALE);
        q0p2 = pk2(z[h*4+2]*QSCALE, z[h*4+2]*QSCALE);
        q0p3 = pk2(z[h*4+3]*QSCALE, z[h*4+3]*QSCALE);
        float4 y0 = xt[2], y1 = xt[3];
        a[0] = y0.x + __ldg(Wq + 0); a[1] = y0.y + __ldg(Wq + 1);
        a[2] = y0.z + __ldg(Wq + 2); a[3] = y0.w + __ldg(Wq + 3);
        a[4] = y1.x + __ldg(Wq + 4); a[5] = y1.y + __ldg(Wq + 5);
        a[6] = y1.z + __ldg(Wq + 6); a[7] = y1.w + __ldg(Wq + 7);
        vqc8(a, z);
        q1p0 = pk2(z[h*4+0]*QSCALE, z[h*4+0]*QSCALE);
        q1p1 = pk2(z[h*4+1]*QSCALE, z[h*4+1]*QSCALE);
        q1p2 = pk2(z[h*4+2]*QSCALE, z[h*4+2]*QSCALE);
        q1p3 = pk2(z[h*4+3]*QSCALE, z[h*4+3]*QSCALE);
    }
    __syncthreads();

    // ---------------- phase 2: attention (2 keys x 2 queries / iter) ---------
    {
        const ulonglong2* K2 = (const ulonglong2*)Ks;
        const ulonglong2* V2 = (const ulonglong2*)Vs;

        u64 sumA = 0ull, a0 = 0ull, a1 = 0ull, a2 = 0ull, a3 = 0ull;
        u64 sumB = 0ull, b0 = 0ull, b1_ = 0ull, b2_ = 0ull, b3 = 0ull;
#pragma unroll 8
        for (int kp = 0; kp < 32; kp++) {
            const int idx = ((kh * 32 + kp) * 2 + h) * 2;  // ulonglong2 units
            ulonglong2 kk0 = K2[idx];
            ulonglong2 kk1 = K2[idx + 1];
            u64 s0 = mul2(q0p0, kk0.x);
            u64 s1 = mul2(q1p0, kk0.x);
            s0 = fma2(q0p1, kk0.y, s0);
            s1 = fma2(q1p1, kk0.y, s1);
            s0 = fma2(q0p2, kk1.x, s0);
            s1 = fma2(q1p2, kk1.x, s1);
            s0 = fma2(q0p3, kk1.y, s0);
            s1 = fma2(q1p3, kk1.y, s1);
            float l0, h0, l1, h1;
            upk2(l0, h0, s0);
            upk2(l1, h1, s1);
            u64 pp0 = pk2(ex2f(l0), ex2f(h0));
            u64 pp1 = pk2(ex2f(l1), ex2f(h1));
            ulonglong2 vv0 = V2[idx];
            ulonglong2 vv1 = V2[idx + 1];
            sumA = add2(sumA, pp0);
            sumB = add2(sumB, pp1);
            a0 = fma2(pp0, vv0.x, a0);
            b0 = fma2(pp1, vv0.x, b0);
            a1 = fma2(pp0, vv0.y, a1);
            b1_ = fma2(pp1, vv0.y, b1_);
            a2 = fma2(pp0, vv1.x, a2);
            b2_ = fma2(pp1, vv1.x, b2_);
            a3 = fma2(pp0, vv1.y, a3);
            b3 = fma2(pp1, vv1.y, b3);
        }
        float cA[5], cB[5];
        { float l, hx; upk2(l, hx, sumA); cA[0] = l + hx; }
        { float l, hx; upk2(l, hx, a0);   cA[1] = l + hx; }
        { float l, hx; upk2(l, hx, a1);   cA[2] = l + hx; }
        { float l, hx; upk2(l, hx, a2);   cA[3] = l + hx; }
        { float l, hx; upk2(l, hx, a3);   cA[4] = l + hx; }
        { float l, hx; upk2(l, hx, sumB); cB[0] = l + hx; }
        { float l, hx; upk2(l, hx, b0);   cB[1] = l + hx; }
        { float l, hx; upk2(l, hx, b1_);  cB[2] = l + hx; }
        { float l, hx; upk2(l, hx, b2_);  cB[3] = l + hx; }
        { float l, hx; upk2(l, hx, b3);   cB[4] = l + hx; }

        const int u0 = qp * 4 + h;       // (query 2qp,   head h)
        const int u1 = qp * 4 + 2 + h;   // (query 2qp+1, head h)
        if (kh != 0) {
            float* p0 = &Part[((kh - 1) * 256 + u0) * 5];
            float* p1 = &Part[((kh - 1) * 256 + u1) * 5];
#pragma unroll
            for (int j = 0; j < 5; j++) { p0[j] = cA[j]; p1[j] = cB[j]; }
        }
        __syncthreads();
        if (kh == 0) {
#pragma unroll
            for (int r = 0; r < 3; r++) {
                const float* p0 = &Part[(r * 256 + u0) * 5];
                const float* p1 = &Part[(r * 256 + u1) * 5];
#pragma unroll
                for (int j = 0; j < 5; j++) { cA[j] += p0[j]; cB[j] += p1[j]; }
            }
            float invA = __fdividef(1.f, cA[0]);
            float invB = __fdividef(1.f, cB[0]);
            float* cxA = &Ctx[(qp * 2) * 8 + h * 4];
            float* cxB = &Ctx[(qp * 2 + 1) * 8 + h * 4];
            cxA[0] = cA[1] * invA; cxA[1] = cA[2] * invA;
            cxA[2] = cA[3] * invA; cxA[3] = cA[4] * invA;
            cxB[0] = cB[1] * invB; cxB[1] = cB[2] * invB;
            cxB[2] = cB[3] * invB; cxB[3] = cB[4] * invB;
        }
        __syncthreads();
    }

    // ---------------- phase 3: tail for 128 local tokens ----------------
    if (tid < QH) {
        const int tok = b * SSEQ + qh * QH + tid;
        float xi[8] = {px0.x, px0.y, px0.z, px0.w, px1.x, px1.y, px1.z, px1.w};

        float a[8], ao[8];
#pragma unroll
        for (int w = 0; w < 8; w++) a[w] = Ctx[tid * 8 + w] + __ldg(Wc + w);
        vqc8(a, ao);

        float y[8], m = 0.f;
#pragma unroll
        for (int w = 0; w < 8; w++) { y[w] = xi[w] + ao[w]; m += y[w]; }
        m *= 0.125f;
        float var = 0.f;
#pragma unroll
        for (int w = 0; w < 8; w++) { float d = y[w] - m; var = fmaf(d, d, var); }
        var *= 0.125f;
        float r = rsqrtf(var + 1e-5f);
        float xn[8];
#pragma unroll
        for (int w = 0; w < 8; w++)
            xn[w] = fmaf((y[w] - m) * r, __ldg(g1 + w), __ldg(be1 + w));

        float hh[8];
#pragma unroll
        for (int i2 = 0; i2 < 8; i2++) {
            float s = __ldg(b1 + i2);
#pragma unroll
            for (int j = 0; j < 8; j++) s = fmaf(xn[j], __ldg(w1 + i2 * 8 + j), s);
            hh[i2] = s;
        }

        float hq[8];
#pragma unroll
        for (int w = 0; w < 8; w++) a[w] = hh[w] + __ldg(Wf + w);
        vqc8(a, hq);

        float z[8], m2 = 0.f;
#pragma unroll
        for (int i2 = 0; i2 < 8; i2++) {
            float s = __ldg(b2 + i2);
#pragma unroll
            for (int j = 0; j < 8; j++) s = fmaf(hq[j], __ldg(w2 + i2 * 8 + j), s);
            z[i2] = xn[i2] + s;
            m2 += z[i2];
        }
        m2 *= 0.125f;
        float v2 = 0.f;
#pragma unroll
        for (int i2 = 0; i2 < 8; i2++) { float d = z[i2] - m2; v2 = fmaf(d, d, v2); }
        v2 *= 0.125f;
        float r2 = rsqrtf(v2 + 1e-5f);
        float o[8];
#pragma unroll
        for (int i2 = 0; i2 < 8; i2++)
            o[i2] = fmaf((z[i2] - m2) * r2, __ldg(g2 + i2), __ldg(be2 + i2));

        float4* op = (float4*)(out + (size_t)tok * EGS);
        op[0] = make_float4(o[0], o[1], o[2], o[3]);
        op[1] = make_float4(o[4], o[5], o[6], o[7]);
    }
}

extern "C" void kernel_launch(void* const* d_in, const int* in_sizes, int n_in,
                              void* d_out, int out_size)
{
    const float* x   = (const float*)d_in[0];
    const float* Wq  = (const float*)d_in[1];
    const float* Wk  = (const float*)d_in[2];
    const float* Wv  = (const float*)d_in[3];
    const float* Wc  = (const float*)d_in[4];
    const float* Wf  = (const float*)d_in[5];
    const float* w1  = (const float*)d_in[6];
    const float* b1  = (const float*)d_in[7];
    const float* w2  = (const float*)d_in[8];
    const float* b2  = (const float*)d_in[9];
    const float* g1  = (const float*)d_in[10];
    const float* be1 = (const float*)d_in[11];
    const float* g2  = (const float*)d_in[12];
    const float* be2 = (const float*)d_in[13];
    float* out = (float*)d_out;

    const int ntok = in_sizes[0] / EGS;   // B*S
    const int nb   = ntok / SSEQ;         // B

    fused_kernel<<<nb * 2, 512>>>(x, Wq, Wk, Wv, Wc, Wf, w1, b1, w2, b2,
                                  g1, be1, g2, be2, out);
}

// round 6
// speedup vs baseline: 1.1599x; 1.1599x over previous
#include <cuda_runtime.h>
#include <math.h>

// ---------------------------------------------------------------------------
// ViTBlockQuantum, fully fused. Analytic collapse of the 8-qubit VQC:
//   phi_w = in_w + theta_w;  z_k = prod_{w=0..k} cos(phi_w) (k>=1),
//   z_0 = prod_{w=1..7} cos(phi_w)
// One kernel: block = (batch, query-half), 1024 threads.
//   phase 1: K (thr 0-255), V (thr 256-511), Q (512-639), consts (640+)
//   phase 2: attention, thread=(query,head,k-quarter); 2 keys/iter f32x2;
//            ex2 software-pipelined one iteration ahead of its consumers
//   phase 3: per-token tail
// ---------------------------------------------------------------------------

#define EGS 8
#define SSEQ 256
#define QH 128
// 0.5 (1/sqrt(dk), dk=4) * log2(e): folded into Q so softmax uses ex2 directly
#define QSCALE 0.72134752044448170368f

typedef unsigned long long u64;

__device__ __forceinline__ float ex2f(float x) {
    float y; asm("ex2.approx.ftz.f32 %0, %1;" : "=f"(y) : "f"(x)); return y;
}
__device__ __forceinline__ u64 pk2(float lo, float hi) {
    u64 r; asm("mov.b64 %0, {%1, %2};" : "=l"(r) : "f"(lo), "f"(hi)); return r;
}
__device__ __forceinline__ void upk2(float& lo, float& hi, u64 v) {
    asm("mov.b64 {%0, %1}, %2;" : "=f"(lo), "=f"(hi) : "l"(v));
}
__device__ __forceinline__ u64 mul2(u64 a, u64 b) {
    u64 d; asm("mul.rn.f32x2 %0, %1, %2;" : "=l"(d) : "l"(a), "l"(b)); return d;
}
__device__ __forceinline__ u64 fma2(u64 a, u64 b, u64 c) {
    u64 d; asm("fma.rn.f32x2 %0, %1, %2, %3;" : "=l"(d) : "l"(a), "l"(b), "l"(c)); return d;
}
__device__ __forceinline__ u64 add2(u64 a, u64 b) {
    u64 d; asm("add.rn.f32x2 %0, %1, %2;" : "=l"(d) : "l"(a), "l"(b)); return d;
}

__device__ __forceinline__ void vqc8(const float a[8], float z[8]) {
    float c[8];
#pragma unroll
    for (int w = 0; w < 8; w++) c[w] = __cosf(a[w]);
    float p = c[0];
#pragma unroll
    for (int k = 1; k < 8; k++) { p *= c[k]; z[k] = p; }
    float q = c[1];
#pragma unroll
    for (int w = 2; w < 8; w++) q *= c[w];
    z[0] = q;
}

// paired K/V smem layout: keys 2k,2k+1 interleaved so one ulonglong2 load
// yields two f32x2 operands (dims d,d+1 for both keys) with zero pack movs
__device__ __forceinline__ int kvidx(int k, int d) {
    return (k >> 1) * 16 + (d >> 2) * 8 + ((d & 2) << 1) + ((d & 1) << 1) + (k & 1);
}

__global__ void __launch_bounds__(1024, 1) fused_kernel(
    const float* __restrict__ x,
    const float* __restrict__ Wq, const float* __restrict__ Wk,
    const float* __restrict__ Wv, const float* __restrict__ Wc,
    const float* __restrict__ Wf,
    const float* __restrict__ w1, const float* __restrict__ b1,
    const float* __restrict__ w2, const float* __restrict__ b2,
    const float* __restrict__ g1, const float* __restrict__ be1,
    const float* __restrict__ g2, const float* __restrict__ be2,
    float* __restrict__ out)
{
    __shared__ __align__(16) float Ks[SSEQ * 8];
    __shared__ __align__(16) float Vs[SSEQ * 8];
    __shared__ __align__(16) float Qs[QH * 8];
    __shared__ float Ctx[QH * 8];
    __shared__ float Part[3 * QH * 2 * 5];   // partials for kh = 1..3
    __shared__ float cw1[64], cw2[64];
    __shared__ float cb1[8], cb2[8], cwc[8], cwf[8];
    __shared__ float cg1[8], cbe1[8], cg2[8], cbe2[8];

    const int b   = blockIdx.x >> 1;
    const int qh  = blockIdx.x & 1;
    const int tid = threadIdx.x;

    // prefetch tail x early (tid<128): hides global latency behind phase 2
    float4 px0 = make_float4(0.f, 0.f, 0.f, 0.f), px1 = px0;
    if (tid < QH) {
        const float4* xt = (const float4*)(x + (size_t)(b * SSEQ + qh * QH + tid) * EGS);
        px0 = xt[0]; px1 = xt[1];
    }

    // ---------------- phase 1: QKV + constant staging (parallel groups) ------
    if (tid < 512) {
        const int t = tid & 255;
        const int isV = tid >> 8;
        const float* W = isV ? Wv : Wk;
        const float4* xt = (const float4*)(x + (size_t)(b * SSEQ + t) * EGS);
        float4 x0 = xt[0], x1 = xt[1];
        float a[8], z[8];
        a[0] = x0.x + __ldg(W + 0); a[1] = x0.y + __ldg(W + 1);
        a[2] = x0.z + __ldg(W + 2); a[3] = x0.w + __ldg(W + 3);
        a[4] = x1.x + __ldg(W + 4); a[5] = x1.y + __ldg(W + 5);
        a[6] = x1.z + __ldg(W + 6); a[7] = x1.w + __ldg(W + 7);
        vqc8(a, z);
        float* dst = isV ? Vs : Ks;
#pragma unroll
        for (int d = 0; d < 8; d++) dst[kvidx(t, d)] = z[d];
    } else if (tid < 640) {
        const int i = tid - 512;
        const float4* xt = (const float4*)(x + (size_t)(b * SSEQ + qh * QH + i) * EGS);
        float4 x0 = xt[0], x1 = xt[1];
        float a[8], z[8];
        a[0] = x0.x + __ldg(Wq + 0); a[1] = x0.y + __ldg(Wq + 1);
        a[2] = x0.z + __ldg(Wq + 2); a[3] = x0.w + __ldg(Wq + 3);
        a[4] = x1.x + __ldg(Wq + 4); a[5] = x1.y + __ldg(Wq + 5);
        a[6] = x1.z + __ldg(Wq + 6); a[7] = x1.w + __ldg(Wq + 7);
        vqc8(a, z);
#pragma unroll
        for (int d = 0; d < 8; d++) Qs[i * 8 + d] = z[d] * QSCALE;
    } else {
        const int j = tid - 640;
        if (j < 64) { cw1[j] = w1[j]; cw2[j] = w2[j]; }
        else if (j < 72) {
            const int k = j - 64;
            cb1[k] = b1[k];  cb2[k] = b2[k];
            cwc[k] = Wc[k];  cwf[k] = Wf[k];
            cg1[k] = g1[k];  cbe1[k] = be1[k];
            cg2[k] = g2[k];  cbe2[k] = be2[k];
        }
    }
    __syncthreads();

    // ---------------- phase 2: attention (skewed ex2 pipeline) ---------------
    {
        const int i  = tid & 127;          // local query
        const int h  = (tid >> 7) & 1;     // head
        const int kh = tid >> 8;           // k-quarter (0..3)

        float4 qv = *(const float4*)&Qs[i * 8 + h * 4];
        u64 qp0 = pk2(qv.x, qv.x), qp1 = pk2(qv.y, qv.y);
        u64 qp2 = pk2(qv.z, qv.z), qp3 = pk2(qv.w, qv.w);

        const ulonglong2* Kp = (const ulonglong2*)Ks + (kh << 7) + (h << 1);
        const ulonglong2* Vp = (const ulonglong2*)Vs + (kh << 7) + (h << 1);

        // prologue: score+exp for pair 0
        ulonglong2 kk0 = Kp[0], kk1 = Kp[1];
        u64 s2 = mul2(qp0, kk0.x);
        s2 = fma2(qp1, kk0.y, s2);
        s2 = fma2(qp2, kk1.x, s2);
        s2 = fma2(qp3, kk1.y, s2);
        float lo, hi; upk2(lo, hi, s2);
        u64 pp = pk2(ex2f(lo), ex2f(hi));

        u64 sum2 = 0ull, cp0 = 0ull, cp1 = 0ull, cp2 = 0ull, cp3 = 0ull;
#pragma unroll 4
        for (int kp = 1; kp < 32; kp++) {
            // next pair's score (independent of pp)
            kk0 = Kp[kp * 4]; kk1 = Kp[kp * 4 + 1];
            u64 s2n = mul2(qp0, kk0.x);
            s2n = fma2(qp1, kk0.y, s2n);
            s2n = fma2(qp2, kk1.x, s2n);
            s2n = fma2(qp3, kk1.y, s2n);
            // accumulate previous pair with pp (ex2 issued last iter)
            ulonglong2 vv0 = Vp[(kp - 1) * 4], vv1 = Vp[(kp - 1) * 4 + 1];
            sum2 = add2(sum2, pp);
            cp0 = fma2(pp, vv0.x, cp0);
            cp1 = fma2(pp, vv0.y, cp1);
            cp2 = fma2(pp, vv1.x, cp2);
            cp3 = fma2(pp, vv1.y, cp3);
            float l2, h2; upk2(l2, h2, s2n);
            pp = pk2(ex2f(l2), ex2f(h2));
        }
        // epilogue: last pair's accumulate
        {
            ulonglong2 vv0 = Vp[31 * 4], vv1 = Vp[31 * 4 + 1];
            sum2 = add2(sum2, pp);
            cp0 = fma2(pp, vv0.x, cp0);
            cp1 = fma2(pp, vv0.y, cp1);
            cp2 = fma2(pp, vv1.x, cp2);
            cp3 = fma2(pp, vv1.y, cp3);
        }

        float sl, sh; upk2(sl, sh, sum2);
        float ssum = sl + sh;
        float c[4];
        { float l, hx; upk2(l, hx, cp0); c[0] = l + hx; }
        { float l, hx; upk2(l, hx, cp1); c[1] = l + hx; }
        { float l, hx; upk2(l, hx, cp2); c[2] = l + hx; }
        { float l, hx; upk2(l, hx, cp3); c[3] = l + hx; }

        if (kh != 0) {
            float* pr = &Part[(((kh - 1) << 8) + i * 2 + h) * 5];
            pr[0] = ssum; pr[1] = c[0]; pr[2] = c[1]; pr[3] = c[2]; pr[4] = c[3];
        }
        __syncthreads();
        if (kh == 0) {
#pragma unroll
            for (int r = 0; r < 3; r++) {
                const float* pr = &Part[((r << 8) + i * 2 + h) * 5];
                ssum += pr[0];
                c[0] += pr[1]; c[1] += pr[2]; c[2] += pr[3]; c[3] += pr[4];
            }
            float inv = __fdividef(1.f, ssum);
            float* cx = &Ctx[i * 8 + h * 4];
            cx[0] = c[0] * inv; cx[1] = c[1] * inv;
            cx[2] = c[2] * inv; cx[3] = c[3] * inv;
        }
        __syncthreads();
    }

    // ---------------- phase 3: tail for 128 local tokens ----------------
    if (tid < QH) {
        const int tok = b * SSEQ + qh * QH + tid;
        float xi[8] = {px0.x, px0.y, px0.z, px0.w, px1.x, px1.y, px1.z, px1.w};

        float a[8], ao[8];
#pragma unroll
        for (int w = 0; w < 8; w++) a[w] = Ctx[tid * 8 + w] + cwc[w];
        vqc8(a, ao);

        float y[8], m = 0.f;
#pragma unroll
        for (int w = 0; w < 8; w++) { y[w] = xi[w] + ao[w]; m += y[w]; }
        m *= 0.125f;
        float var = 0.f;
#pragma unroll
        for (int w = 0; w < 8; w++) { float d = y[w] - m; var = fmaf(d, d, var); }
        var *= 0.125f;
        float r = rsqrtf(var + 1e-5f);
        float xn[8];
#pragma unroll
        for (int w = 0; w < 8; w++) xn[w] = fmaf((y[w] - m) * r, cg1[w], cbe1[w]);

        float hh[8];
#pragma unroll
        for (int i2 = 0; i2 < 8; i2++) {
            float s = cb1[i2];
#pragma unroll
            for (int j = 0; j < 8; j++) s = fmaf(xn[j], cw1[i2 * 8 + j], s);
            hh[i2] = s;
        }

        float hq[8];
#pragma unroll
        for (int w = 0; w < 8; w++) a[w] = hh[w] + cwf[w];
        vqc8(a, hq);

        float z[8], m2 = 0.f;
#pragma unroll
        for (int i2 = 0; i2 < 8; i2++) {
            float s = cb2[i2];
#pragma unroll
            for (int j = 0; j < 8; j++) s = fmaf(hq[j], cw2[i2 * 8 + j], s);
            z[i2] = xn[i2] + s;
            m2 += z[i2];
        }
        m2 *= 0.125f;
        float v2 = 0.f;
#pragma unroll
        for (int i2 = 0; i2 < 8; i2++) { float d = z[i2] - m2; v2 = fmaf(d, d, v2); }
        v2 *= 0.125f;
        float r2 = rsqrtf(v2 + 1e-5f);
        float o[8];
#pragma unroll
        for (int i2 = 0; i2 < 8; i2++) o[i2] = fmaf((z[i2] - m2) * r2, cg2[i2], cbe2[i2]);

        float4* op = (float4*)(out + (size_t)tok * EGS);
        op[0] = make_float4(o[0], o[1], o[2], o[3]);
        op[1] = make_float4(o[4], o[5], o[6], o[7]);
    }
}

extern "C" void kernel_launch(void* const* d_in, const int* in_sizes, int n_in,
                              void* d_out, int out_size)
{
    const float* x   = (const float*)d_in[0];
    const float* Wq  = (const float*)d_in[1];
    const float* Wk  = (const float*)d_in[2];
    const float* Wv  = (const float*)d_in[3];
    const float* Wc  = (const float*)d_in[4];
    const float* Wf  = (const float*)d_in[5];
    const float* w1  = (const float*)d_in[6];
    const float* b1  = (const float*)d_in[7];
    const float* w2  = (const float*)d_in[8];
    const float* b2  = (const float*)d_in[9];
    const float* g1  = (const float*)d_in[10];
    const float* be1 = (const float*)d_in[11];
    const float* g2  = (const float*)d_in[12];
    const float* be2 = (const float*)d_in[13];
    float* out = (float*)d_out;

    const int ntok = in_sizes[0] / EGS;   // B*S
    const int nb   = ntok / SSEQ;         // B

    fused_kernel<<<nb * 2, 1024>>>(x, Wq, Wk, Wv, Wc, Wf, w1, b1, w2, b2,
                                   g1, be1, g2, be2, out);
}

// round 7
// speedup vs baseline: 1.1910x; 1.0269x over previous
#include <cuda_runtime.h>
#include <math.h>

// ---------------------------------------------------------------------------
// ViTBlockQuantum, fully fused. Analytic collapse of the 8-qubit VQC:
//   phi_w = in_w + theta_w;  z_k = prod_{w=0..k} cos(phi_w) (k>=1),
//   z_0 = prod_{w=1..7} cos(phi_w)
// One kernel: block = (batch, query-half), 1024 threads.
//   phase 1: K (thr 0-255), V (256-511), Q (512-639), consts (640+)
//   phase 2: thread = (query-pair, head, k-eighth); 2 keys x 2 queries per
//            iter, f32x2-packed, K/V LDS amortized over 2 queries
//   phase 3: per-token tail
// ---------------------------------------------------------------------------

#define EGS 8
#define SSEQ 256
#define QH 128
// 0.5 (1/sqrt(dk), dk=4) * log2(e): folded into Q so softmax uses ex2 directly
#define QSCALE 0.72134752044448170368f

typedef unsigned long long u64;

__device__ __forceinline__ float ex2f(float x) {
    float y; asm("ex2.approx.ftz.f32 %0, %1;" : "=f"(y) : "f"(x)); return y;
}
__device__ __forceinline__ u64 pk2(float lo, float hi) {
    u64 r; asm("mov.b64 %0, {%1, %2};" : "=l"(r) : "f"(lo), "f"(hi)); return r;
}
__device__ __forceinline__ void upk2(float& lo, float& hi, u64 v) {
    asm("mov.b64 {%0, %1}, %2;" : "=f"(lo), "=f"(hi) : "l"(v));
}
__device__ __forceinline__ u64 mul2(u64 a, u64 b) {
    u64 d; asm("mul.rn.f32x2 %0, %1, %2;" : "=l"(d) : "l"(a), "l"(b)); return d;
}
__device__ __forceinline__ u64 fma2(u64 a, u64 b, u64 c) {
    u64 d; asm("fma.rn.f32x2 %0, %1, %2, %3;" : "=l"(d) : "l"(a), "l"(b), "l"(c)); return d;
}
__device__ __forceinline__ u64 add2(u64 a, u64 b) {
    u64 d; asm("add.rn.f32x2 %0, %1, %2;" : "=l"(d) : "l"(a), "l"(b)); return d;
}

__device__ __forceinline__ void vqc8(const float a[8], float z[8]) {
    float c[8];
#pragma unroll
    for (int w = 0; w < 8; w++) c[w] = __cosf(a[w]);
    float p = c[0];
#pragma unroll
    for (int k = 1; k < 8; k++) { p *= c[k]; z[k] = p; }
    float q = c[1];
#pragma unroll
    for (int w = 2; w < 8; w++) q *= c[w];
    z[0] = q;
}

// paired K/V smem layout: keys 2k,2k+1 interleaved; key-pair kp = 4 ulonglong2:
//   u2#(kp*4 + h*2 + j) = packed (dim 2j, dim 2j+1) f32x2 pairs for head h
__device__ __forceinline__ int kvidx(int k, int d) {
    return (k >> 1) * 16 + (d >> 2) * 8 + ((d & 2) << 1) + ((d & 1) << 1) + (k & 1);
}

// Part unit layout: unit = h*128 + (q&1)*64 + (q>>1)  -> lane stride 1 unit
#define PUNIT(q, h) (((h) << 7) + (((q) & 1) << 6) + ((q) >> 1))

__global__ void __launch_bounds__(1024, 1) fused_kernel(
    const float* __restrict__ x,
    const float* __restrict__ Wq, const float* __restrict__ Wk,
    const float* __restrict__ Wv, const float* __restrict__ Wc,
    const float* __restrict__ Wf,
    const float* __restrict__ w1, const float* __restrict__ b1,
    const float* __restrict__ w2, const float* __restrict__ b2,
    const float* __restrict__ g1, const float* __restrict__ be1,
    const float* __restrict__ g2, const float* __restrict__ be2,
    float* __restrict__ out)
{
    __shared__ __align__(16) float Ks[SSEQ * 8];
    __shared__ __align__(16) float Vs[SSEQ * 8];
    __shared__ __align__(16) float Qs[QH * 8];
    __shared__ float Ctx[QH * 8];
    __shared__ float Part[7 * 256 * 5];      // kh = 1..7 partials
    __shared__ float cw1[64], cw2[64];
    __shared__ float cb1[8], cb2[8], cwc[8], cwf[8];
    __shared__ float cg1[8], cbe1[8], cg2[8], cbe2[8];

    const int b   = blockIdx.x >> 1;
    const int qh  = blockIdx.x & 1;
    const int tid = threadIdx.x;

    // prefetch tail x early (tid<128): hides global latency behind phase 2
    float4 px0 = make_float4(0.f, 0.f, 0.f, 0.f), px1 = px0;
    if (tid < QH) {
        const float4* xt = (const float4*)(x + (size_t)(b * SSEQ + qh * QH + tid) * EGS);
        px0 = xt[0]; px1 = xt[1];
    }

    // ---------------- phase 1: QKV + constant staging (parallel groups) ------
    if (tid < 512) {
        const int t = tid & 255;
        const int isV = tid >> 8;
        const float* W = isV ? Wv : Wk;
        const float4* xt = (const float4*)(x + (size_t)(b * SSEQ + t) * EGS);
        float4 x0 = xt[0], x1 = xt[1];
        float a[8], z[8];
        a[0] = x0.x + __ldg(W + 0); a[1] = x0.y + __ldg(W + 1);
        a[2] = x0.z + __ldg(W + 2); a[3] = x0.w + __ldg(W + 3);
        a[4] = x1.x + __ldg(W + 4); a[5] = x1.y + __ldg(W + 5);
        a[6] = x1.z + __ldg(W + 6); a[7] = x1.w + __ldg(W + 7);
        vqc8(a, z);
        float* dst = isV ? Vs : Ks;
#pragma unroll
        for (int d = 0; d < 8; d++) dst[kvidx(t, d)] = z[d];
    } else if (tid < 640) {
        const int i = tid - 512;
        const float4* xt = (const float4*)(x + (size_t)(b * SSEQ + qh * QH + i) * EGS);
        float4 x0 = xt[0], x1 = xt[1];
        float a[8], z[8];
        a[0] = x0.x + __ldg(Wq + 0); a[1] = x0.y + __ldg(Wq + 1);
        a[2] = x0.z + __ldg(Wq + 2); a[3] = x0.w + __ldg(Wq + 3);
        a[4] = x1.x + __ldg(Wq + 4); a[5] = x1.y + __ldg(Wq + 5);
        a[6] = x1.z + __ldg(Wq + 6); a[7] = x1.w + __ldg(Wq + 7);
        vqc8(a, z);
#pragma unroll
        for (int d = 0; d < 8; d++) Qs[i * 8 + d] = z[d] * QSCALE;
    } else {
        const int j = tid - 640;
        if (j < 64) { cw1[j] = w1[j]; cw2[j] = w2[j]; }
        else if (j < 72) {
            const int k = j - 64;
            cb1[k] = b1[k];  cb2[k] = b2[k];
            cwc[k] = Wc[k];  cwf[k] = Wf[k];
            cg1[k] = g1[k];  cbe1[k] = be1[k];
            cg2[k] = g2[k];  cbe2[k] = be2[k];
        }
    }
    __syncthreads();

    // ---------------- phase 2: attention (2 keys x 2 queries / iter) ---------
    {
        const int qp = tid & 63;           // query pair (queries 2qp, 2qp+1)
        const int h  = (tid >> 6) & 1;     // head
        const int kh = tid >> 7;           // k-eighth (0..7)

        // Q operands from smem (one-time)
        float4 qA = *(const float4*)&Qs[(qp * 2) * 8 + h * 4];
        float4 qB = *(const float4*)&Qs[(qp * 2 + 1) * 8 + h * 4];
        u64 qA0 = pk2(qA.x, qA.x), qA1 = pk2(qA.y, qA.y);
        u64 qA2 = pk2(qA.z, qA.z), qA3 = pk2(qA.w, qA.w);
        u64 qB0 = pk2(qB.x, qB.x), qB1 = pk2(qB.y, qB.y);
        u64 qB2 = pk2(qB.z, qB.z), qB3 = pk2(qB.w, qB.w);

        const ulonglong2* Kp = (const ulonglong2*)Ks + (kh << 6) + (h << 1);
        const ulonglong2* Vp = (const ulonglong2*)Vs + (kh << 6) + (h << 1);

        u64 sumA = 0ull, a0 = 0ull, a1 = 0ull, a2 = 0ull, a3 = 0ull;
        u64 sumB = 0ull, b0 = 0ull, b1_ = 0ull, b2_ = 0ull, b3_ = 0ull;
#pragma unroll 8
        for (int kp = 0; kp < 16; kp++) {
            ulonglong2 kk0 = Kp[kp * 4], kk1 = Kp[kp * 4 + 1];
            u64 s0 = mul2(qA0, kk0.x);
            u64 s1 = mul2(qB0, kk0.x);
            s0 = fma2(qA1, kk0.y, s0);
            s1 = fma2(qB1, kk0.y, s1);
            s0 = fma2(qA2, kk1.x, s0);
            s1 = fma2(qB2, kk1.x, s1);
            s0 = fma2(qA3, kk1.y, s0);
            s1 = fma2(qB3, kk1.y, s1);
            float l0, h0, l1, h1;
            upk2(l0, h0, s0);
            upk2(l1, h1, s1);
            u64 pp0 = pk2(ex2f(l0), ex2f(h0));
            u64 pp1 = pk2(ex2f(l1), ex2f(h1));
            ulonglong2 vv0 = Vp[kp * 4], vv1 = Vp[kp * 4 + 1];
            sumA = add2(sumA, pp0);
            sumB = add2(sumB, pp1);
            a0 = fma2(pp0, vv0.x, a0);
            b0 = fma2(pp1, vv0.x, b0);
            a1 = fma2(pp0, vv0.y, a1);
            b1_ = fma2(pp1, vv0.y, b1_);
            a2 = fma2(pp0, vv1.x, a2);
            b2_ = fma2(pp1, vv1.x, b2_);
            a3 = fma2(pp0, vv1.y, a3);
            b3_ = fma2(pp1, vv1.y, b3_);
        }
        float cA[5], cB[5];
        { float l, hx; upk2(l, hx, sumA); cA[0] = l + hx; }
        { float l, hx; upk2(l, hx, a0);   cA[1] = l + hx; }
        { float l, hx; upk2(l, hx, a1);   cA[2] = l + hx; }
        { float l, hx; upk2(l, hx, a2);   cA[3] = l + hx; }
        { float l, hx; upk2(l, hx, a3);   cA[4] = l + hx; }
        { float l, hx; upk2(l, hx, sumB); cB[0] = l + hx; }
        { float l, hx; upk2(l, hx, b0);   cB[1] = l + hx; }
        { float l, hx; upk2(l, hx, b1_);  cB[2] = l + hx; }
        { float l, hx; upk2(l, hx, b2_);  cB[3] = l + hx; }
        { float l, hx; upk2(l, hx, b3_);  cB[4] = l + hx; }

        const int uA = PUNIT(qp * 2, h);
        const int uB = PUNIT(qp * 2 + 1, h);
        if (kh != 0) {
            float* p0 = &Part[((kh - 1) * 256 + uA) * 5];
            float* p1 = &Part[((kh - 1) * 256 + uB) * 5];
#pragma unroll
            for (int j = 0; j < 5; j++) { p0[j] = cA[j]; p1[j] = cB[j]; }
        }
        __syncthreads();
        if (kh == 0) {
#pragma unroll
            for (int r = 0; r < 7; r++) {
                const float* p0 = &Part[(r * 256 + uA) * 5];
                const float* p1 = &Part[(r * 256 + uB) * 5];
#pragma unroll
                for (int j = 0; j < 5; j++) { cA[j] += p0[j]; cB[j] += p1[j]; }
            }
            float invA = __fdividef(1.f, cA[0]);
            float invB = __fdividef(1.f, cB[0]);
            float* cxA = &Ctx[(qp * 2) * 8 + h * 4];
            float* cxB = &Ctx[(qp * 2 + 1) * 8 + h * 4];
            cxA[0] = cA[1] * invA; cxA[1] = cA[2] * invA;
            cxA[2] = cA[3] * invA; cxA[3] = cA[4] * invA;
            cxB[0] = cB[1] * invB; cxB[1] = cB[2] * invB;
            cxB[2] = cB[3] * invB; cxB[3] = cB[4] * invB;
        }
        __syncthreads();
    }

    // ---------------- phase 3: tail for 128 local tokens ----------------
    if (tid < QH) {
        const int tok = b * SSEQ + qh * QH + tid;
        float xi[8] = {px0.x, px0.y, px0.z, px0.w, px1.x, px1.y, px1.z, px1.w};

        float a[8], ao[8];
#pragma unroll
        for (int w = 0; w < 8; w++) a[w] = Ctx[tid * 8 + w] + cwc[w];
        vqc8(a, ao);

        float y[8], m = 0.f;
#pragma unroll
        for (int w = 0; w < 8; w++) { y[w] = xi[w] + ao[w]; m += y[w]; }
        m *= 0.125f;
        float var = 0.f;
#pragma unroll
        for (int w = 0; w < 8; w++) { float d = y[w] - m; var = fmaf(d, d, var); }
        var *= 0.125f;
        float r = rsqrtf(var + 1e-5f);
        float xn[8];
#pragma unroll
        for (int w = 0; w < 8; w++) xn[w] = fmaf((y[w] - m) * r, cg1[w], cbe1[w]);

        float hh[8];
#pragma unroll
        for (int i2 = 0; i2 < 8; i2++) {
            float s = cb1[i2];
#pragma unroll
            for (int j = 0; j < 8; j++) s = fmaf(xn[j], cw1[i2 * 8 + j], s);
            hh[i2] = s;
        }

        float hq[8];
#pragma unroll
        for (int w = 0; w < 8; w++) a[w] = hh[w] + cwf[w];
        vqc8(a, hq);

        float z[8], m2 = 0.f;
#pragma unroll
        for (int i2 = 0; i2 < 8; i2++) {
            float s = cb2[i2];
#pragma unroll
            for (int j = 0; j < 8; j++) s = fmaf(hq[j], cw2[i2 * 8 + j], s);
            z[i2] = xn[i2] + s;
            m2 += z[i2];
        }
        m2 *= 0.125f;
        float v2 = 0.f;
#pragma unroll
        for (int i2 = 0; i2 < 8; i2++) { float d = z[i2] - m2; v2 = fmaf(d, d, v2); }
        v2 *= 0.125f;
        float r2 = rsqrtf(v2 + 1e-5f);
        float o[8];
#pragma unroll
        for (int i2 = 0; i2 < 8; i2++) o[i2] = fmaf((z[i2] - m2) * r2, cg2[i2], cbe2[i2]);

        float4* op = (float4*)(out + (size_t)tok * EGS);
        op[0] = make_float4(o[0], o[1], o[2], o[3]);
        op[1] = make_float4(o[4], o[5], o[6], o[7]);
    }
}

extern "C" void kernel_launch(void* const* d_in, const int* in_sizes, int n_in,
                              void* d_out, int out_size)
{
    const float* x   = (const float*)d_in[0];
    const float* Wq  = (const float*)d_in[1];
    const float* Wk  = (const float*)d_in[2];
    const float* Wv  = (const float*)d_in[3];
    const float* Wc  = (const float*)d_in[4];
    const float* Wf  = (const float*)d_in[5];
    const float* w1  = (const float*)d_in[6];
    const float* b1  = (const float*)d_in[7];
    const float* w2  = (const float*)d_in[8];
    const float* b2  = (const float*)d_in[9];
    const float* g1  = (const float*)d_in[10];
    const float* be1 = (const float*)d_in[11];
    const float* g2  = (const float*)d_in[12];
    const float* be2 = (const float*)d_in[13];
    float* out = (float*)d_out;

    const int ntok = in_sizes[0] / EGS;   // B*S
    const int nb   = ntok / SSEQ;         // B

    fused_kernel<<<nb * 2, 1024>>>(x, Wq, Wk, Wv, Wc, Wf, w1, b1, w2, b2,
                                   g1, be1, g2, be2, out);
}